// round 16
// baseline (speedup 1.0000x reference)
#include <cuda_runtime.h>
#include <math.h>

// Problem constants
#define NB    64
#define NIMG  4096    // NB*64
#define HW    49
#define NC    128
#define NS    8
#define NK    512
#define NE    64
#define NT    63

#define CONV_SMEM (128*108*4)

typedef unsigned long long ull;

__device__ __forceinline__ ull packf2(float lo, float hi) {
    ull d;
    asm("mov.b64 %0, {%1, %2};" : "=l"(d)
        : "r"(__float_as_uint(lo)), "r"(__float_as_uint(hi)));
    return d;
}
__device__ __forceinline__ void unpackf2(ull d, float& lo, float& hi) {
    unsigned int a, b;
    asm("mov.b64 {%0, %1}, %2;" : "=r"(a), "=r"(b) : "l"(d));
    lo = __uint_as_float(a); hi = __uint_as_float(b);
}
__device__ __forceinline__ unsigned smem_u32(const void* p) {
    unsigned a;
    asm("{ .reg .u64 t; cvta.to.shared.u64 t, %1; cvt.u32.u64 %0, t; }"
        : "=r"(a) : "l"(p));
    return a;
}
#define FFMA2(d, a, b) asm("fma.rn.f32x2 %0, %1, %2, %0;" : "+l"(d) : "l"(a), "l"(b))

// ---------------- device scratch ----------------
__device__ float g_X1[NIMG*HW*NC];     // conv1 output (~98MB)
__device__ float g_EW[441*9*128];      // emb @ conv1_w table (2MB)
__device__ ull   g_wdup[9*128*128];    // conv2 weights duplicated (w,w)
__device__ float g_cmax[NIMG*NC];
__device__ float g_cmin[NIMG*NC];
__device__ float g_obs_feat[NIMG*NC];
__device__ float g_gi[NIMG*192];
__device__ float g_bn1_sum[NC];
__device__ float g_bn1_sq[NC];
__device__ float g_bn2_sum[NC];
__device__ float g_bn2_sq[NC];
__device__ float g_z_all[NT*NB*512];   // 8.3MB: full z rollout (VQ-independent)
__device__ float g_cb[NS*NK*NE];
__device__ float g_csA[NS*NK];
__device__ float g_csB[NS*NK];
__device__ float g_ea[NS*NK*NE];
__device__ float g_cntA[NK];
__device__ float g_cntB[NK];
__device__ float g_sumA[NK*NE];
__device__ float g_sumB[NK*NE];
__device__ float g_pd[64*64];
__device__ int   g_pi[64*64];
__device__ float g_zq_all[NT*NB*512];  // 8.3MB: zq per (t,b)
__device__ float g_gab_g[NT*NB*NC];
__device__ float g_gab_b[NT*NB*NC];
__device__ double g_decl;
__device__ double g_el;
__device__ unsigned g_bar_cnt;
__device__ unsigned g_bar_gen;

// ---------------- prep: duplicate conv2 weights + zero bn stats ----------
__global__ void k_wdup(const float* __restrict__ w2) {
    int i = blockIdx.x * blockDim.x + threadIdx.x;
    if (i < 9*128*128) { float v = w2[i]; g_wdup[i] = packf2(v, v); }
    if (i < NC) { g_bn1_sum[i]=0.f; g_bn1_sq[i]=0.f; g_bn2_sum[i]=0.f; g_bn2_sq[i]=0.f; }
}

// ---------------- EW[e][tap][co] = sum_ci emb[e][ci] * w1[tap][ci][co] ----
__global__ __launch_bounds__(128) void k_ew(const float* __restrict__ emb,
                                            const float* __restrict__ w1) {
    int e = blockIdx.x, co = threadIdx.x;
    __shared__ float es[128];
    es[co] = emb[e*128 + co];
    __syncthreads();
    #pragma unroll
    for (int tap = 0; tap < 9; tap++) {
        float a = 0.f;
        for (int ci = 0; ci < 128; ci++)
            a = fmaf(es[ci], w1[(tap*128 + ci)*128 + co], a);
        g_EW[(e*9 + tap)*128 + co] = a;
    }
}

// ---------------- conv1 via EW gather, 256 thr: rows 0-3 / 4-6 split -----
__global__ __launch_bounds__(256) void k_conv1g(const int* __restrict__ obs,
                                                const float* __restrict__ b1) {
    int n = blockIdx.x;
    int co = threadIdx.x & 127, grp = threadIdx.x >> 7;
    int b = n >> 6, t = n & 63;
    __shared__ int sidx[3*HW];           // (obs + plane*147) * 9, pre-scaled
    for (int j = threadIdx.x; j < 3*HW; j += 256) {
        int pl = j / HW, pos = j % HW;
        sidx[j] = (obs[(((b*65 + t)*3 + pl)*HW) + pos] + pl * 147) * 9;
    }
    __syncthreads();
    float bv = b1[co];
    float s = 0.f, s2 = 0.f;
    float* op = g_X1 + (size_t)n * HW * NC;
    int oh0 = grp ? 4 : 0, oh1 = grp ? 7 : 4;
    for (int oh = oh0; oh < oh1; oh++) {
        for (int ow = 0; ow < 7; ow++) {
            float a = bv;
            #pragma unroll
            for (int kh = 0; kh < 3; kh++) {
                int ih = oh + kh - 1;
                if (ih < 0 || ih > 6) continue;
                #pragma unroll
                for (int kw = 0; kw < 3; kw++) {
                    int iw = ow + kw - 1;
                    if (iw < 0 || iw > 6) continue;
                    int q = ih*7 + iw, tap = kh*3 + kw;
                    a += __ldg(&g_EW[(sidx[q]      + tap)*128 + co])
                       + __ldg(&g_EW[(sidx[HW + q] + tap)*128 + co])
                       + __ldg(&g_EW[(sidx[2*HW+q] + tap)*128 + co]);
                }
            }
            op[(oh*7 + ow)*NC + co] = a;
            s += a; s2 = fmaf(a, a, s2);
        }
    }
    atomicAdd(&g_bn1_sum[co], s);
    atomicAdd(&g_bn1_sq[co], s2);
}

// ---------------- conv2 mainloop over compile-time row range -------------
// Even pairs:  (o0,o1)(o2,o3)(o4,o5)(o6,j)   <- kw=0 (E0..E3), kw=2 (E1,E2,E3,P8)
// Shift pairs: (j,o0)(o1,o2)(o3,o4)(o5,o6)   <- kw=1 (E0..E3)
template<int OH0, int NOH>
__device__ __forceinline__ void conv2_main(unsigned pbase, ull bp, int co,
        float& s, float& s2, float& mx, float& mn) {
    ull accE[NOH][4], accS[NOH][4];
    #pragma unroll
    for (int o = 0; o < NOH; o++) {
        #pragma unroll
        for (int j = 0; j < 4; j++) { accE[o][j] = bp; accS[o][j] = 0ull; }
    }
    for (int ci = 0; ci < NC; ci++) {
        ull wp[9];
        #pragma unroll
        for (int tap = 0; tap < 9; tap++)
            wp[tap] = g_wdup[(tap*NC + ci)*NC + co];
        unsigned rb = pbase + ci*432;
        #pragma unroll
        for (int r = OH0; r < OH0 + NOH + 2; r++) {
            ull E0, E1, E2, E3, P8;
            unsigned a0 = rb + r*48;
            asm volatile("ld.shared.v2.b64 {%0,%1},[%2];" : "=l"(E0), "=l"(E1) : "r"(a0));
            asm volatile("ld.shared.v2.b64 {%0,%1},[%2];" : "=l"(E2), "=l"(E3) : "r"(a0 + 16));
            asm volatile("ld.shared.b64 %0,[%1];" : "=l"(P8) : "r"(a0 + 32));
            #pragma unroll
            for (int kh = 0; kh < 3; kh++) {
                int oh = r - kh;
                if (oh < OH0 || oh > OH0 + NOH - 1) continue;
                int ol = oh - OH0;
                ull w0 = wp[kh*3+0], w1_ = wp[kh*3+1], w2_ = wp[kh*3+2];
                FFMA2(accE[ol][0], E0, w0);  FFMA2(accE[ol][1], E1, w0);
                FFMA2(accE[ol][2], E2, w0);  FFMA2(accE[ol][3], E3, w0);
                FFMA2(accS[ol][0], E0, w1_); FFMA2(accS[ol][1], E1, w1_);
                FFMA2(accS[ol][2], E2, w1_); FFMA2(accS[ol][3], E3, w1_);
                FFMA2(accE[ol][0], E1, w2_); FFMA2(accE[ol][1], E2, w2_);
                FFMA2(accE[ol][2], E3, w2_); FFMA2(accE[ol][3], P8, w2_);
            }
        }
    }
    #pragma unroll
    for (int o = 0; o < NOH; o++) {
        float e0l,e0h,e1l,e1h,e2l,e2h,e3l,e3h;
        float s0l,s0h,s1l,s1h,s2l,s2h,s3l,s3h;
        unpackf2(accE[o][0], e0l, e0h);
        unpackf2(accE[o][1], e1l, e1h);
        unpackf2(accE[o][2], e2l, e2h);
        unpackf2(accE[o][3], e3l, e3h);
        unpackf2(accS[o][0], s0l, s0h);
        unpackf2(accS[o][1], s1l, s1h);
        unpackf2(accS[o][2], s2l, s2h);
        unpackf2(accS[o][3], s3l, s3h);
        float v[7];
        v[0] = e0l + s0h;  v[1] = e0h + s1l;  v[2] = e1l + s1h;
        v[3] = e1h + s2l;  v[4] = e2l + s2h;  v[5] = e2h + s3l;
        v[6] = e3l + s3h;
        #pragma unroll
        for (int ow = 0; ow < 7; ow++) {
            float x = v[ow];
            s += x; s2 = fmaf(x, x, s2);
            mx = fmaxf(mx, x); mn = fminf(mn, x);
        }
    }
}

// ---------------- conv2: 128 thr, two temporal passes (rows 0-3, 4-6) ----
__global__ __launch_bounds__(128, 4) void k_conv2(
        const float* __restrict__ bias,
        const float* __restrict__ bng, const float* __restrict__ bnb) {
    extern __shared__ float P[];                 // 128*108 floats
    int n  = blockIdx.x;
    int co = threadIdx.x;

    const float invN = 1.f / 200704.f;
    float m  = g_bn1_sum[co] * invN;
    float va = g_bn1_sq[co] * invN - m*m;
    float sc = bng[co] * rsqrtf(va + 1e-5f);
    float sh = bnb[co] - m * sc;

    #pragma unroll
    for (int q = 0; q < 108; q++) P[co*108 + q] = 0.f;
    const float* inp = g_X1 + (size_t)n * HW * NC;
    #pragma unroll 7
    for (int pos = 0; pos < HW; pos++) {
        float v = fmaxf(fmaf(inp[pos*NC + co], sc, sh), 0.f);
        int h = pos / 7, wv = pos % 7;
        P[co*108 + (h+1)*12 + (wv+1)] = v;
    }
    __syncthreads();

    unsigned pbase = smem_u32(P);
    float bv = bias[co];
    ull bp = packf2(bv, bv);
    float s = 0.f, s2 = 0.f, mx = -3.4e38f, mn = 3.4e38f;
    conv2_main<0,4>(pbase, bp, co, s, s2, mx, mn);
    conv2_main<4,3>(pbase, bp, co, s, s2, mx, mn);

    g_cmax[n*NC + co] = mx;
    g_cmin[n*NC + co] = mn;
    atomicAdd(&g_bn2_sum[co], s);
    atomicAdd(&g_bn2_sq[co], s2);
}

// ---------------- init ----------------
__global__ void k_init_a(const float* __restrict__ codebook) {
    int i = blockIdx.x * blockDim.x + threadIdx.x;
    if (i < NS*NK*NE) { g_cb[i] = codebook[i]; g_ea[i] = codebook[i]; }
}
__global__ void k_init_b() {
    int i = blockIdx.x * blockDim.x + threadIdx.x;
    if (i < NS*NK) { g_csA[i] = 0.f; g_csB[i] = 0.f; }
    if (i == 0) { g_decl = 0.0; g_el = 0.0; g_bar_cnt = 0u; g_bar_gen = 0u; }
}
__global__ void k_init_cde() {
    int i = blockIdx.x * blockDim.x + threadIdx.x;
    if (i < NK) { g_cntA[i] = 0.f; g_cntB[i] = 0.f; }
    if (i < NK*NE) { g_sumA[i] = 0.f; g_sumB[i] = 0.f; }
}

// ---------------- bn2 + maxpool + relu -> obs_feat ----------------
__global__ void k_bn2max(const float* __restrict__ bng, const float* __restrict__ bnb) {
    int i = blockIdx.x * blockDim.x + threadIdx.x;
    if (i >= NIMG*NC) return;
    int c = i & 127;
    const float invN = 1.f / 200704.f;
    float m  = g_bn2_sum[c] * invN;
    float va = g_bn2_sq[c] * invN - m*m;
    float sc = bng[c] * rsqrtf(va + 1e-5f);
    float sh = bnb[c] - m * sc;
    float raw = (sc >= 0.f) ? g_cmax[i] : g_cmin[i];
    g_obs_feat[i] = fmaxf(fmaf(raw, sc, sh), 0.f);
}

// ---------------- gi = obs_feat @ Wih^T + bih ----------------
__global__ __launch_bounds__(192) void k_gi(const float* __restrict__ wih,
                                            const float* __restrict__ bih) {
    int n0 = blockIdx.x * 8;
    int j = threadIdx.x;
    __shared__ float xs[8*128];
    for (int i = j; i < 1024; i += 192) xs[i] = g_obs_feat[n0*128 + i];
    __syncthreads();
    float acc[8];
    float bv = bih[j];
    #pragma unroll
    for (int r = 0; r < 8; r++) acc[r] = bv;
    for (int i = 0; i < 128; i++) {
        float wv = wih[j*128 + i];
        #pragma unroll
        for (int r = 0; r < 8; r++) acc[r] = fmaf(xs[r*128 + i], wv, acc[r]);
    }
    #pragma unroll
    for (int r = 0; r < 8; r++) g_gi[(n0 + r)*192 + j] = acc[r];
}

// ---------------- full GRU rollout: z(t) for ALL t (VQ-independent) ------
__global__ __launch_bounds__(256) void k_zroll(
        const float* __restrict__ whh, const float* __restrict__ bhh,
        const float* __restrict__ prew, const float* __restrict__ preb) {
    int b = blockIdx.x, tid = threadIdx.x;
    __shared__ float hs[64], gh[192];
    if (tid < 64) hs[tid] = 0.f;
    __syncthreads();
    for (int t = 0; t < NT; t++) {
        if (tid < 192) {
            float a = bhh[tid];
            for (int i = 0; i < 64; i++) a = fmaf(hs[i], whh[tid*64 + i], a);
            gh[tid] = a;
        }
        __syncthreads();
        if (tid < 64) {
            const float* gi = g_gi + ((size_t)(b*64 + t))*192;
            float r  = 1.f / (1.f + expf(-(gi[tid] + gh[tid])));
            float zz = 1.f / (1.f + expf(-(gi[64 + tid] + gh[64 + tid])));
            float nn = tanhf(gi[128 + tid] + r * gh[128 + tid]);
            hs[tid] = (1.f - zz) * nn + zz * hs[tid];
        }
        __syncthreads();
        float* zp = g_z_all + ((size_t)t*NB + b)*512;
        #pragma unroll
        for (int rep = 0; rep < 2; rep++) {
            int j = tid + rep*256;
            float a = preb[j];
            for (int i = 0; i < 64; i++) a = fmaf(hs[i], prew[i*512 + j], a);
            zp[j] = a;
        }
        __syncthreads();
    }
}

// ---------------- grid barrier: atomic arrive, LIGHT ld.cg poll ----------
__device__ __forceinline__ void grid_barrier(unsigned &gen) {
    __syncthreads();
    if (threadIdx.x == 0) {
        __threadfence();
        unsigned arrived = atomicAdd(&g_bar_cnt, 1u);
        if (arrived == 63u) {
            atomicExch(&g_bar_cnt, 0u);
            __threadfence();
            atomicExch(&g_bar_gen, gen + 1u);
        } else {
            unsigned v;
            do {
                asm volatile("ld.global.cg.u32 %0, [%1];" : "=r"(v) : "l"(&g_bar_gen));
            } while (v < gen + 1u);
        }
        __threadfence();
    }
    gen++;
    __syncthreads();
}

// ---------------- persistent scan: VQ + EMA only ----------------
// All cross-block data accessed ONLY via __ldcg/__stcg/atomics.
__global__ __launch_bounds__(256) void k_scan() {
    __shared__ float cbs[64*64];
    __shared__ float zsh[64*65];
    __shared__ float red[256];
    __shared__ float invc[64];
    __shared__ float pdl[4*64];
    __shared__ int   pil[4*64];
    __shared__ int   kmin[8];
    __shared__ float dmin[8];

    unsigned gen = 0;
    int tid = threadIdx.x;

    for (int t = 0; t < NT; t++) {
        const float* zt = g_z_all + (size_t)t*NB*512;
        // ================= phase A: bid = (s, kc) =================
        {
            int s = blockIdx.x >> 3, kc = blockIdx.x & 7;
            const float* csr  = (t & 1) ? g_csB : g_csA;
            float*       csw  = (t & 1) ? g_csA : g_csB;
            const float* cntp = (t & 1) ? g_cntA : g_cntB;
            const float* sump = (t & 1) ? g_sumA : g_sumB;
            float*       cntc = (t & 1) ? g_cntB : g_cntA;
            float*       sumc = (t & 1) ? g_sumB : g_sumA;

            if (tid < 8) __stcg(&cntc[blockIdx.x*8 + tid], 0.f);
            if (tid < 128) __stcg(&reinterpret_cast<float4*>(sumc + blockIdx.x*512)[tid],
                                  make_float4(0.f,0.f,0.f,0.f));

            #pragma unroll
            for (int rep = 0; rep < 16; rep++) {
                int j = tid + rep*256;
                int bb = j >> 6, e = j & 63;
                zsh[e*65 + bb] = __ldcg(&zt[bb*512 + s*64 + e]);
            }

            if (t > 0) {
                float c1 = fmaf(0.01f, __ldcg(&cntp[tid]),       __ldcg(&csr[s*NK + tid])       * 0.99f);
                float c2 = fmaf(0.01f, __ldcg(&cntp[tid + 256]), __ldcg(&csr[s*NK + tid + 256]) * 0.99f);
                red[tid] = c1 + c2;
                __syncthreads();
                for (int off = 128; off > 0; off >>= 1) {
                    if (tid < off) red[tid] += red[tid + off];
                    __syncthreads();
                }
                float ntot = red[0];
                if (tid < 64) {
                    int k = kc*64 + tid;
                    float cs_new = fmaf(0.01f, __ldcg(&cntp[k]), __ldcg(&csr[s*NK + k]) * 0.99f);
                    __stcg(&csw[s*NK + k], cs_new);
                    float csn = (cs_new + 1e-5f) / (ntot + 512.f * 1e-5f) * ntot;
                    invc[tid] = 1.f / csn;
                }
                __syncthreads();
                float4* ea4  = reinterpret_cast<float4*>(g_ea + ((size_t)s*NK + kc*64)*NE);
                float4* cbg4 = reinterpret_cast<float4*>(g_cb + ((size_t)s*NK + kc*64)*NE);
                const float4* sm4 = reinterpret_cast<const float4*>(sump + kc*64*NE);
                float4* cbs4 = reinterpret_cast<float4*>(cbs);
                #pragma unroll
                for (int rep = 0; rep < 4; rep++) {
                    int j = tid + rep*256;
                    float inv = invc[j >> 4];
                    float4 e = ea4[j];            // block-private
                    float4 sv = __ldcg(&sm4[j]);
                    e.x = fmaf(0.01f, sv.x, e.x*0.99f);
                    e.y = fmaf(0.01f, sv.y, e.y*0.99f);
                    e.z = fmaf(0.01f, sv.z, e.z*0.99f);
                    e.w = fmaf(0.01f, sv.w, e.w*0.99f);
                    ea4[j] = e;
                    float4 cv = make_float4(e.x*inv, e.y*inv, e.z*inv, e.w*inv);
                    __stcg(&cbg4[j], cv);
                    cbs4[j] = cv;
                }
            } else {
                const float4* cbg4 = reinterpret_cast<const float4*>(g_cb + ((size_t)s*NK + kc*64)*NE);
                float4* cbs4 = reinterpret_cast<float4*>(cbs);
                #pragma unroll
                for (int rep = 0; rep < 4; rep++) cbs4[tid + rep*256] = __ldcg(&cbg4[tid + rep*256]);
            }
            __syncthreads();

            int b  = tid & 63;
            int kg = tid >> 6;
            float zreg[64];
            #pragma unroll
            for (int e = 0; e < 64; e++) zreg[e] = zsh[e*65 + b];
            float best = 3.4e38f; int bk = 0;
            #pragma unroll 4
            for (int j = 0; j < 16; j++) {
                int kl = kg*16 + j;
                const float4* row = reinterpret_cast<const float4*>(cbs + kl*64);
                float d = 0.f;
                #pragma unroll
                for (int e4 = 0; e4 < 16; e4++) {
                    float4 c = row[e4];
                    float dx = zreg[4*e4]   - c.x; d = fmaf(dx, dx, d);
                    dx = zreg[4*e4+1] - c.y; d = fmaf(dx, dx, d);
                    dx = zreg[4*e4+2] - c.z; d = fmaf(dx, dx, d);
                    dx = zreg[4*e4+3] - c.w; d = fmaf(dx, dx, d);
                }
                if (d < best) { best = d; bk = kl; }
            }
            pdl[kg*64 + b] = best; pil[kg*64 + b] = bk;
            __syncthreads();
            if (tid < 64) {
                float bd = pdl[tid]; int bi = pil[tid];
                #pragma unroll
                for (int g = 1; g < 4; g++) {
                    float d2 = pdl[g*64 + tid];
                    if (d2 < bd) { bd = d2; bi = pil[g*64 + tid]; }
                }
                __stcg(&g_pd[blockIdx.x*64 + tid], bd);
                __stcg(&g_pi[blockIdx.x*64 + tid], kc*64 + bi);
            }
        }
        grid_barrier(gen);

        // ================= phase B: bid = b (finalize + stats + zq) =======
        {
            int b = blockIdx.x;
            float* cntc = (t & 1) ? g_cntB : g_cntA;
            float* sumc = (t & 1) ? g_sumB : g_sumA;

            // parallel finalize: tid<64 = (s, kc2); reduce width 8 via shfl
            if (tid < 64) {
                int s = tid >> 3, kc2 = tid & 7;
                float bd = __ldcg(&g_pd[(s*8 + kc2)*64 + b]);
                int   bi = __ldcg(&g_pi[(s*8 + kc2)*64 + b]);
                #pragma unroll
                for (int off = 4; off > 0; off >>= 1) {
                    float d2 = __shfl_down_sync(0xFFFFFFFFu, bd, off, 8);
                    int   k2 = __shfl_down_sync(0xFFFFFFFFu, bi, off, 8);
                    if (d2 < bd || (d2 == bd && k2 < bi)) { bd = d2; bi = k2; }
                }
                if (kc2 == 0) {
                    kmin[s] = bi; dmin[s] = bd;
                    atomicAdd(&cntc[bi], 1.0f);
                }
            }
            __syncthreads();
            if (tid == 0) {
                double e = 0.0;
                #pragma unroll
                for (int s = 0; s < 8; s++) e += (double)dmin[s];
                atomicAdd(&g_el, e * (1.0 / 32768.0));
            }
            #pragma unroll
            for (int rep = 0; rep < 2; rep++) {
                int j = tid + rep*256;
                int s = j >> 6, e = j & 63;
                int k = kmin[s];
                float zqv = __ldcg(&g_cb[((size_t)s*NK + k)*NE + e]);
                __stcg(&g_zq_all[((size_t)t*64 + b)*512 + j], zqv);
                atomicAdd(&sumc[k*64 + e], __ldcg(&zt[b*512 + j]));
            }
        }
        grid_barrier(gen);
    }
}

// ---------------- batched FiLM MLP over all (t,b): 8 rows/block ----------
__global__ __launch_bounds__(256) void k_mlpall(
        const float* __restrict__ m1w, const float* __restrict__ m1b,
        const float* __restrict__ m2w, const float* __restrict__ m2b) {
    int row0 = blockIdx.x * 8;          // 4032 rows total
    int tid = threadIdx.x;
    __shared__ float zq[8][512];
    __shared__ float h1s[8][128];
    {
        float4* dst = reinterpret_cast<float4*>(&zq[0][0]);
        const float4* src = reinterpret_cast<const float4*>(g_zq_all + (size_t)row0*512);
        #pragma unroll
        for (int rep = 0; rep < 4; rep++) dst[tid + rep*256] = src[tid + rep*256];
    }
    __syncthreads();
    {
        int col = tid & 127, half = tid >> 7;
        int r0 = half*4;
        float acc[4];
        float bv = m1b[col];
        #pragma unroll
        for (int r = 0; r < 4; r++) acc[r] = bv;
        for (int i = 0; i < 512; i++) {
            float wv = m1w[i*128 + col];
            #pragma unroll
            for (int r = 0; r < 4; r++) acc[r] = fmaf(zq[r0 + r][i], wv, acc[r]);
        }
        #pragma unroll
        for (int r = 0; r < 4; r++) h1s[r0 + r][col] = fmaxf(acc[r], 0.f);
    }
    __syncthreads();
    {
        float acc2[8];
        float bv = m2b[tid];
        #pragma unroll
        for (int r = 0; r < 8; r++) acc2[r] = bv;
        for (int i = 0; i < 128; i++) {
            float wv = m2w[i*256 + tid];
            #pragma unroll
            for (int r = 0; r < 8; r++) acc2[r] = fmaf(h1s[r][i], wv, acc2[r]);
        }
        #pragma unroll
        for (int r = 0; r < 8; r++) {
            int rr = row0 + r;          // = t*64 + b
            if (tid < 128) g_gab_g[(size_t)rr*128 + tid] = 1.f + acc2[r];
            else           g_gab_b[(size_t)rr*128 + (tid - 128)] = acc2[r];
        }
    }
}

// ---------------- batched decoder, 16 rows/block ----------------
__global__ __launch_bounds__(128) void k_dec(const int* __restrict__ acts,
        const float* __restrict__ w1, const float* __restrict__ b1,
        const float* __restrict__ w2, const float* __restrict__ b2,
        const float* __restrict__ w3, const float* __restrict__ b3) {
    int row0 = blockIdx.x * 16;
    int tp = row0 >> 6;
    int b0 = row0 & 63;
    float sq = sqrtf((float)(127*127 - 8*tp));
    int t = (int)((127.0f - sq) * 0.5f);
    while ((t+1)*(127-(t+1))/2 <= tp && t < 62) t++;
    while (t*(127-t)/2 > tp) t--;
    int p = t + (tp - t*(127-t)/2);
    int c = threadIdx.x;
    __shared__ float f[16][128];
    __shared__ float h1[16][128];
    __shared__ float h2[16][128];
    __shared__ float lg[16][6];
    __shared__ float ce[16];
    #pragma unroll
    for (int j = 0; j < 16; j++) {
        int b = b0 + j;
        float of = g_obs_feat[(b*64 + p)*NC + c];
        float fl = fmaf(of, g_gab_g[((size_t)t*64 + b)*128 + c],
                            g_gab_b[((size_t)t*64 + b)*128 + c]);
        f[j][c] = fmaxf(fl, 0.f);
    }
    __syncthreads();
    float acc[16];
    float bv = b1[c];
    #pragma unroll
    for (int j = 0; j < 16; j++) acc[j] = bv;
    for (int i = 0; i < 128; i += 4) {
        float wa = w1[i*128 + c], wb = w1[(i+1)*128 + c];
        float wc = w1[(i+2)*128 + c], wd = w1[(i+3)*128 + c];
        #pragma unroll
        for (int j = 0; j < 16; j++) {
            float4 fv = *reinterpret_cast<const float4*>(&f[j][i]);
            acc[j] = fmaf(fv.x, wa, fmaf(fv.y, wb, fmaf(fv.z, wc, fmaf(fv.w, wd, acc[j]))));
        }
    }
    #pragma unroll
    for (int j = 0; j < 16; j++) h1[j][c] = fmaxf(acc[j], 0.f);
    __syncthreads();
    bv = b2[c];
    #pragma unroll
    for (int j = 0; j < 16; j++) acc[j] = bv;
    for (int i = 0; i < 128; i += 4) {
        float wa = w2[i*128 + c], wb = w2[(i+1)*128 + c];
        float wc = w2[(i+2)*128 + c], wd = w2[(i+3)*128 + c];
        #pragma unroll
        for (int j = 0; j < 16; j++) {
            float4 fv = *reinterpret_cast<const float4*>(&h1[j][i]);
            acc[j] = fmaf(fv.x, wa, fmaf(fv.y, wb, fmaf(fv.z, wc, fmaf(fv.w, wd, acc[j]))));
        }
    }
    #pragma unroll
    for (int j = 0; j < 16; j++) h2[j][c] = fmaxf(acc[j], 0.f);
    __syncthreads();
    if (c < 96) {
        int j = c / 6, o = c % 6;
        float l = b3[o];
        for (int i = 0; i < 128; i++) l = fmaf(h2[j][i], w3[i*6 + o], l);
        lg[j][o] = l;
    }
    __syncthreads();
    if (c < 16) {
        int b = b0 + c;
        float m = lg[c][0];
        #pragma unroll
        for (int i = 1; i < 6; i++) m = fmaxf(m, lg[c][i]);
        float se = 0.f;
        #pragma unroll
        for (int i = 0; i < 6; i++) se += expf(lg[c][i] - m);
        float lse = m + logf(se);
        int a = acts[b*63 + p];
        ce[c] = lse - lg[c][a];
    }
    __syncthreads();
    if (c == 0) {
        double ssum = 0.0;
        #pragma unroll
        for (int j = 0; j < 16; j++) ssum += (double)ce[j];
        atomicAdd(&g_decl, ssum);
    }
}

// ---------------- finalize ----------------
__global__ void k_final(float* __restrict__ out) {
    if (threadIdx.x == 0) {
        out[0] = (float)(g_decl / 64.0);
        out[1] = (float)(g_el / 64.0);
    }
}

// ---------------- launch ----------------
extern "C" void kernel_launch(void* const* d_in, const int* in_sizes, int n_in,
                              void* d_out, int out_size) {
    const int*   obs  = (const int*)d_in[0];
    const int*   acts = (const int*)d_in[1];
    const float* emb  = (const float*)d_in[2];
    const float* c1w  = (const float*)d_in[3];
    const float* c1b  = (const float*)d_in[4];
    const float* bn1g = (const float*)d_in[5];
    const float* bn1b = (const float*)d_in[6];
    const float* c2w  = (const float*)d_in[7];
    const float* c2b  = (const float*)d_in[8];
    const float* bn2g = (const float*)d_in[9];
    const float* bn2b = (const float*)d_in[10];
    const float* wih  = (const float*)d_in[11];
    const float* whh  = (const float*)d_in[12];
    const float* bih  = (const float*)d_in[13];
    const float* bhh  = (const float*)d_in[14];
    const float* prew = (const float*)d_in[15];
    const float* preb = (const float*)d_in[16];
    const float* cbk  = (const float*)d_in[17];
    const float* m1w  = (const float*)d_in[18];
    const float* m1b  = (const float*)d_in[19];
    const float* m2w  = (const float*)d_in[20];
    const float* m2b  = (const float*)d_in[21];
    const float* d1w  = (const float*)d_in[22];
    const float* d1b  = (const float*)d_in[23];
    const float* d2w  = (const float*)d_in[24];
    const float* d2b  = (const float*)d_in[25];
    const float* d3w  = (const float*)d_in[26];
    const float* d3b  = (const float*)d_in[27];
    float* out = (float*)d_out;

    cudaFuncSetAttribute(k_conv2, cudaFuncAttributeMaxDynamicSharedMemorySize, CONV_SMEM);

    k_wdup<<<576, 256>>>(c2w);                                   // 1: dup w2 + zero bn stats
    k_ew<<<441, 128>>>(emb, c1w);                                // 2: EW table
    k_conv1g<<<NIMG, 256>>>(obs, c1b);                           // 3: conv1 gather + bn1 stats
    k_conv2<<<NIMG, 128, CONV_SMEM>>>(c2b, bn2g, bn2b);          // 4: conv2 (ncu slot)
    k_init_a<<<1024, 256>>>(cbk);
    k_init_b<<<16, 256>>>();
    k_init_cde<<<128, 256>>>();
    k_bn2max<<<(NIMG*NC + 255)/256, 256>>>(bn2g, bn2b);
    k_gi<<<NIMG/8, 192>>>(wih, bih);
    k_zroll<<<NB, 256>>>(whh, bhh, prew, preb);
    k_scan<<<64, 256>>>();
    k_mlpall<<<NT*NB/8, 256>>>(m1w, m1b, m2w, m2b);
    k_dec<<<129024/16, 128>>>(acts, d1w, d1b, d2w, d2b, d3w, d3b);
    k_final<<<1, 32>>>(out);
}

// round 17
// speedup vs baseline: 1.0448x; 1.0448x over previous
#include <cuda_runtime.h>
#include <math.h>

// Problem constants
#define NB    64
#define NIMG  4096    // NB*64
#define HW    49
#define NC    128
#define NS    8
#define NK    512
#define NE    64
#define NT    63

#define CONV_SMEM (128*108*4)

typedef unsigned long long ull;

__device__ __forceinline__ ull packf2(float lo, float hi) {
    ull d;
    asm("mov.b64 %0, {%1, %2};" : "=l"(d)
        : "r"(__float_as_uint(lo)), "r"(__float_as_uint(hi)));
    return d;
}
__device__ __forceinline__ void unpackf2(ull d, float& lo, float& hi) {
    unsigned int a, b;
    asm("mov.b64 {%0, %1}, %2;" : "=r"(a), "=r"(b) : "l"(d));
    lo = __uint_as_float(a); hi = __uint_as_float(b);
}
__device__ __forceinline__ unsigned smem_u32(const void* p) {
    unsigned a;
    asm("{ .reg .u64 t; cvta.to.shared.u64 t, %1; cvt.u32.u64 %0, t; }"
        : "=r"(a) : "l"(p));
    return a;
}
#define FFMA2(d, a, b) asm("fma.rn.f32x2 %0, %1, %2, %0;" : "+l"(d) : "l"(a), "l"(b))

// ---------------- device scratch ----------------
__device__ float g_X1[NIMG*HW*NC];     // conv1 output (~98MB)
__device__ float g_EW[441*9*128];      // emb @ conv1_w table (2MB)
__device__ ull   g_wdup[9*128*128];    // conv2 weights duplicated (w,w)
__device__ float g_cmax[NIMG*NC];
__device__ float g_cmin[NIMG*NC];
__device__ float g_obs_feat[NIMG*NC];
__device__ float g_gi[NIMG*192];
__device__ float g_bn1_sum[NC];
__device__ float g_bn1_sq[NC];
__device__ float g_bn2_sum[NC];
__device__ float g_bn2_sq[NC];
__device__ float g_z_all[NT*NB*512];   // 8.3MB: full z rollout (VQ-independent)
__device__ float g_cb[NS*NK*NE];
__device__ float g_csA[NS*NK];
__device__ float g_csB[NS*NK];
__device__ float g_ea[NS*NK*NE];
__device__ float g_cntA[NK];
__device__ float g_cntB[NK];
__device__ float g_sumA[NK*NE];
__device__ float g_sumB[NK*NE];
__device__ float g_pd[64*64];
__device__ int   g_pi[64*64];
__device__ float g_zq_all[NT*NB*512];  // 8.3MB: zq per (t,b)
__device__ float g_gab_g[NT*NB*NC];
__device__ float g_gab_b[NT*NB*NC];
__device__ double g_decl;
__device__ double g_el;
__device__ unsigned g_bar_cnt;
__device__ unsigned g_bar_gen;

// ---------------- prep: duplicate conv2 weights + zero bn stats ----------
__global__ void k_wdup(const float* __restrict__ w2) {
    int i = blockIdx.x * blockDim.x + threadIdx.x;
    if (i < 9*128*128) { float v = w2[i]; g_wdup[i] = packf2(v, v); }
    if (i < NC) { g_bn1_sum[i]=0.f; g_bn1_sq[i]=0.f; g_bn2_sum[i]=0.f; g_bn2_sq[i]=0.f; }
}

// ---------------- EW[e][tap][co] = sum_ci emb[e][ci] * w1[tap][ci][co] ----
__global__ __launch_bounds__(128) void k_ew(const float* __restrict__ emb,
                                            const float* __restrict__ w1) {
    int e = blockIdx.x, co = threadIdx.x;
    __shared__ float es[128];
    es[co] = emb[e*128 + co];
    __syncthreads();
    #pragma unroll
    for (int tap = 0; tap < 9; tap++) {
        float a = 0.f;
        for (int ci = 0; ci < 128; ci++)
            a = fmaf(es[ci], w1[(tap*128 + ci)*128 + co], a);
        g_EW[(e*9 + tap)*128 + co] = a;
    }
}

// ---------------- conv1 via EW gather, 256 thr: rows 0-3 / 4-6 split -----
__global__ __launch_bounds__(256) void k_conv1g(const int* __restrict__ obs,
                                                const float* __restrict__ b1) {
    int n = blockIdx.x;
    int co = threadIdx.x & 127, grp = threadIdx.x >> 7;
    int b = n >> 6, t = n & 63;
    __shared__ int sidx[3*HW];           // (obs + plane*147) * 9, pre-scaled
    for (int j = threadIdx.x; j < 3*HW; j += 256) {
        int pl = j / HW, pos = j % HW;
        sidx[j] = (obs[(((b*65 + t)*3 + pl)*HW) + pos] + pl * 147) * 9;
    }
    __syncthreads();
    float bv = b1[co];
    float s = 0.f, s2 = 0.f;
    float* op = g_X1 + (size_t)n * HW * NC;
    int oh0 = grp ? 4 : 0, oh1 = grp ? 7 : 4;
    for (int oh = oh0; oh < oh1; oh++) {
        for (int ow = 0; ow < 7; ow++) {
            float a = bv;
            #pragma unroll
            for (int kh = 0; kh < 3; kh++) {
                int ih = oh + kh - 1;
                if (ih < 0 || ih > 6) continue;
                #pragma unroll
                for (int kw = 0; kw < 3; kw++) {
                    int iw = ow + kw - 1;
                    if (iw < 0 || iw > 6) continue;
                    int q = ih*7 + iw, tap = kh*3 + kw;
                    a += __ldg(&g_EW[(sidx[q]      + tap)*128 + co])
                       + __ldg(&g_EW[(sidx[HW + q] + tap)*128 + co])
                       + __ldg(&g_EW[(sidx[2*HW+q] + tap)*128 + co]);
                }
            }
            op[(oh*7 + ow)*NC + co] = a;
            s += a; s2 = fmaf(a, a, s2);
        }
    }
    atomicAdd(&g_bn1_sum[co], s);
    atomicAdd(&g_bn1_sq[co], s2);
}

// ---------------- conv2: shifted-accumulator FFMA2 (frozen R10 version) --
__global__ __launch_bounds__(128) void k_conv2(
        const float* __restrict__ bias,
        const float* __restrict__ bng, const float* __restrict__ bnb) {
    extern __shared__ float P[];                 // 128*108 floats
    int n  = blockIdx.x;
    int co = threadIdx.x;

    const float invN = 1.f / 200704.f;
    float m  = g_bn1_sum[co] * invN;
    float va = g_bn1_sq[co] * invN - m*m;
    float sc = bng[co] * rsqrtf(va + 1e-5f);
    float sh = bnb[co] - m * sc;

    #pragma unroll
    for (int q = 0; q < 108; q++) P[co*108 + q] = 0.f;
    const float* inp = g_X1 + (size_t)n * HW * NC;
    #pragma unroll 7
    for (int pos = 0; pos < HW; pos++) {
        float v = fmaxf(fmaf(inp[pos*NC + co], sc, sh), 0.f);
        int h = pos / 7, wv = pos % 7;
        P[co*108 + (h+1)*12 + (wv+1)] = v;
    }
    __syncthreads();

    unsigned pbase = smem_u32(P);
    float bv = bias[co];
    ull bp = packf2(bv, bv);
    ull accE[7][4], accS[7][4];
    #pragma unroll
    for (int oh = 0; oh < 7; oh++) {
        #pragma unroll
        for (int j = 0; j < 4; j++) { accE[oh][j] = bp; accS[oh][j] = 0ull; }
    }

    for (int ci = 0; ci < NC; ci++) {
        ull wp[9];
        #pragma unroll
        for (int tap = 0; tap < 9; tap++)
            wp[tap] = g_wdup[(tap*NC + ci)*NC + co];
        unsigned rb = pbase + ci*432;
        #pragma unroll
        for (int r = 0; r < 9; r++) {
            ull E0, E1, E2, E3, P8;
            unsigned a0 = rb + r*48;
            asm volatile("ld.shared.v2.b64 {%0,%1},[%2];" : "=l"(E0), "=l"(E1) : "r"(a0));
            asm volatile("ld.shared.v2.b64 {%0,%1},[%2];" : "=l"(E2), "=l"(E3) : "r"(a0 + 16));
            asm volatile("ld.shared.b64 %0,[%1];" : "=l"(P8) : "r"(a0 + 32));
            #pragma unroll
            for (int kh = 0; kh < 3; kh++) {
                int oh = r - kh;
                if (oh < 0 || oh > 6) continue;
                ull w0 = wp[kh*3+0], w1_ = wp[kh*3+1], w2_ = wp[kh*3+2];
                FFMA2(accE[oh][0], E0, w0);  FFMA2(accE[oh][1], E1, w0);
                FFMA2(accE[oh][2], E2, w0);  FFMA2(accE[oh][3], E3, w0);
                FFMA2(accS[oh][0], E0, w1_); FFMA2(accS[oh][1], E1, w1_);
                FFMA2(accS[oh][2], E2, w1_); FFMA2(accS[oh][3], E3, w1_);
                FFMA2(accE[oh][0], E1, w2_); FFMA2(accE[oh][1], E2, w2_);
                FFMA2(accE[oh][2], E3, w2_); FFMA2(accE[oh][3], P8, w2_);
            }
        }
    }

    float s = 0.f, s2 = 0.f;
    float mx = -3.4e38f, mn = 3.4e38f;
    #pragma unroll
    for (int oh = 0; oh < 7; oh++) {
        float e0l,e0h,e1l,e1h,e2l,e2h,e3l,e3h;
        float s0l,s0h,s1l,s1h,s2l,s2h,s3l,s3h;
        unpackf2(accE[oh][0], e0l, e0h);
        unpackf2(accE[oh][1], e1l, e1h);
        unpackf2(accE[oh][2], e2l, e2h);
        unpackf2(accE[oh][3], e3l, e3h);
        unpackf2(accS[oh][0], s0l, s0h);
        unpackf2(accS[oh][1], s1l, s1h);
        unpackf2(accS[oh][2], s2l, s2h);
        unpackf2(accS[oh][3], s3l, s3h);
        float v[7];
        v[0] = e0l + s0h;  v[1] = e0h + s1l;  v[2] = e1l + s1h;
        v[3] = e1h + s2l;  v[4] = e2l + s2h;  v[5] = e2h + s3l;
        v[6] = e3l + s3h;
        #pragma unroll
        for (int ow = 0; ow < 7; ow++) {
            float x = v[ow];
            s += x; s2 = fmaf(x, x, s2);
            mx = fmaxf(mx, x); mn = fminf(mn, x);
        }
    }
    g_cmax[n*NC + co] = mx;
    g_cmin[n*NC + co] = mn;
    atomicAdd(&g_bn2_sum[co], s);
    atomicAdd(&g_bn2_sq[co], s2);
}

// ---------------- init ----------------
__global__ void k_init_a(const float* __restrict__ codebook) {
    int i = blockIdx.x * blockDim.x + threadIdx.x;
    if (i < NS*NK*NE) { g_cb[i] = codebook[i]; g_ea[i] = codebook[i]; }
}
__global__ void k_init_b() {
    int i = blockIdx.x * blockDim.x + threadIdx.x;
    if (i < NS*NK) { g_csA[i] = 0.f; g_csB[i] = 0.f; }
    if (i == 0) { g_decl = 0.0; g_el = 0.0; g_bar_cnt = 0u; g_bar_gen = 0u; }
}
__global__ void k_init_cde() {
    int i = blockIdx.x * blockDim.x + threadIdx.x;
    if (i < NK) { g_cntA[i] = 0.f; g_cntB[i] = 0.f; }
    if (i < NK*NE) { g_sumA[i] = 0.f; g_sumB[i] = 0.f; }
}

// ---------------- bn2 + maxpool + relu -> obs_feat ----------------
__global__ void k_bn2max(const float* __restrict__ bng, const float* __restrict__ bnb) {
    int i = blockIdx.x * blockDim.x + threadIdx.x;
    if (i >= NIMG*NC) return;
    int c = i & 127;
    const float invN = 1.f / 200704.f;
    float m  = g_bn2_sum[c] * invN;
    float va = g_bn2_sq[c] * invN - m*m;
    float sc = bng[c] * rsqrtf(va + 1e-5f);
    float sh = bnb[c] - m * sc;
    float raw = (sc >= 0.f) ? g_cmax[i] : g_cmin[i];
    g_obs_feat[i] = fmaxf(fmaf(raw, sc, sh), 0.f);
}

// ---------------- gi = obs_feat @ Wih^T + bih ----------------
__global__ __launch_bounds__(192) void k_gi(const float* __restrict__ wih,
                                            const float* __restrict__ bih) {
    int n0 = blockIdx.x * 8;
    int j = threadIdx.x;
    __shared__ float xs[8*128];
    for (int i = j; i < 1024; i += 192) xs[i] = g_obs_feat[n0*128 + i];
    __syncthreads();
    float acc[8];
    float bv = bih[j];
    #pragma unroll
    for (int r = 0; r < 8; r++) acc[r] = bv;
    for (int i = 0; i < 128; i++) {
        float wv = wih[j*128 + i];
        #pragma unroll
        for (int r = 0; r < 8; r++) acc[r] = fmaf(xs[r*128 + i], wv, acc[r]);
    }
    #pragma unroll
    for (int r = 0; r < 8; r++) g_gi[(n0 + r)*192 + j] = acc[r];
}

// ---------------- full GRU rollout: z(t) for ALL t (VQ-independent) ------
__global__ __launch_bounds__(256) void k_zroll(
        const float* __restrict__ whh, const float* __restrict__ bhh,
        const float* __restrict__ prew, const float* __restrict__ preb) {
    int b = blockIdx.x, tid = threadIdx.x;
    __shared__ float hs[64], gh[192];
    if (tid < 64) hs[tid] = 0.f;
    __syncthreads();
    for (int t = 0; t < NT; t++) {
        if (tid < 192) {
            float a = bhh[tid];
            for (int i = 0; i < 64; i++) a = fmaf(hs[i], whh[tid*64 + i], a);
            gh[tid] = a;
        }
        __syncthreads();
        if (tid < 64) {
            const float* gi = g_gi + ((size_t)(b*64 + t))*192;
            float r  = 1.f / (1.f + expf(-(gi[tid] + gh[tid])));
            float zz = 1.f / (1.f + expf(-(gi[64 + tid] + gh[64 + tid])));
            float nn = tanhf(gi[128 + tid] + r * gh[128 + tid]);
            hs[tid] = (1.f - zz) * nn + zz * hs[tid];
        }
        __syncthreads();
        float* zp = g_z_all + ((size_t)t*NB + b)*512;
        #pragma unroll
        for (int rep = 0; rep < 2; rep++) {
            int j = tid + rep*256;
            float a = preb[j];
            for (int i = 0; i < 64; i++) a = fmaf(hs[i], prew[i*512 + j], a);
            zp[j] = a;
        }
        __syncthreads();
    }
}

// ---------------- grid barrier: atomic arrive, LIGHT ld.cg poll ----------
__device__ __forceinline__ void grid_barrier(unsigned &gen) {
    __syncthreads();
    if (threadIdx.x == 0) {
        __threadfence();
        unsigned arrived = atomicAdd(&g_bar_cnt, 1u);
        if (arrived == 63u) {
            atomicExch(&g_bar_cnt, 0u);
            __threadfence();
            atomicExch(&g_bar_gen, gen + 1u);
        } else {
            unsigned v;
            do {
                asm volatile("ld.global.cg.u32 %0, [%1];" : "=r"(v) : "l"(&g_bar_gen));
            } while (v < gen + 1u);
        }
        __threadfence();
    }
    gen++;
    __syncthreads();
}

// ---------------- persistent scan: VQ + EMA only ----------------
// All cross-block data accessed ONLY via __ldcg/__stcg/atomics.
__global__ __launch_bounds__(256) void k_scan() {
    __shared__ float cbs[64*64];
    __shared__ float zsh[64*65];
    __shared__ float red[256];
    __shared__ float invc[64];
    __shared__ float pdl[4*64];
    __shared__ int   pil[4*64];
    __shared__ int   kmin[8];
    __shared__ float dmin[8];

    unsigned gen = 0;
    int tid = threadIdx.x;

    for (int t = 0; t < NT; t++) {
        const float* zt = g_z_all + (size_t)t*NB*512;
        // ================= phase A: bid = (s, kc) =================
        {
            int s = blockIdx.x >> 3, kc = blockIdx.x & 7;
            const float* csr  = (t & 1) ? g_csB : g_csA;
            float*       csw  = (t & 1) ? g_csA : g_csB;
            const float* cntp = (t & 1) ? g_cntA : g_cntB;
            const float* sump = (t & 1) ? g_sumA : g_sumB;
            float*       cntc = (t & 1) ? g_cntB : g_cntA;
            float*       sumc = (t & 1) ? g_sumB : g_sumA;

            if (tid < 8) __stcg(&cntc[blockIdx.x*8 + tid], 0.f);
            if (tid < 128) __stcg(&reinterpret_cast<float4*>(sumc + blockIdx.x*512)[tid],
                                  make_float4(0.f,0.f,0.f,0.f));

            #pragma unroll
            for (int rep = 0; rep < 16; rep++) {
                int j = tid + rep*256;
                int bb = j >> 6, e = j & 63;
                zsh[e*65 + bb] = __ldcg(&zt[bb*512 + s*64 + e]);
            }

            if (t > 0) {
                float c1 = fmaf(0.01f, __ldcg(&cntp[tid]),       __ldcg(&csr[s*NK + tid])       * 0.99f);
                float c2 = fmaf(0.01f, __ldcg(&cntp[tid + 256]), __ldcg(&csr[s*NK + tid + 256]) * 0.99f);
                red[tid] = c1 + c2;
                __syncthreads();
                for (int off = 128; off > 0; off >>= 1) {
                    if (tid < off) red[tid] += red[tid + off];
                    __syncthreads();
                }
                float ntot = red[0];
                if (tid < 64) {
                    int k = kc*64 + tid;
                    float cs_new = fmaf(0.01f, __ldcg(&cntp[k]), __ldcg(&csr[s*NK + k]) * 0.99f);
                    __stcg(&csw[s*NK + k], cs_new);
                    float csn = (cs_new + 1e-5f) / (ntot + 512.f * 1e-5f) * ntot;
                    invc[tid] = 1.f / csn;
                }
                __syncthreads();
                float4* ea4  = reinterpret_cast<float4*>(g_ea + ((size_t)s*NK + kc*64)*NE);
                float4* cbg4 = reinterpret_cast<float4*>(g_cb + ((size_t)s*NK + kc*64)*NE);
                const float4* sm4 = reinterpret_cast<const float4*>(sump + kc*64*NE);
                float4* cbs4 = reinterpret_cast<float4*>(cbs);
                #pragma unroll
                for (int rep = 0; rep < 4; rep++) {
                    int j = tid + rep*256;
                    float inv = invc[j >> 4];
                    float4 e = ea4[j];            // block-private
                    float4 sv = __ldcg(&sm4[j]);
                    e.x = fmaf(0.01f, sv.x, e.x*0.99f);
                    e.y = fmaf(0.01f, sv.y, e.y*0.99f);
                    e.z = fmaf(0.01f, sv.z, e.z*0.99f);
                    e.w = fmaf(0.01f, sv.w, e.w*0.99f);
                    ea4[j] = e;
                    float4 cv = make_float4(e.x*inv, e.y*inv, e.z*inv, e.w*inv);
                    __stcg(&cbg4[j], cv);
                    cbs4[j] = cv;
                }
            } else {
                const float4* cbg4 = reinterpret_cast<const float4*>(g_cb + ((size_t)s*NK + kc*64)*NE);
                float4* cbs4 = reinterpret_cast<float4*>(cbs);
                #pragma unroll
                for (int rep = 0; rep < 4; rep++) cbs4[tid + rep*256] = __ldcg(&cbg4[tid + rep*256]);
            }
            __syncthreads();

            int b  = tid & 63;
            int kg = tid >> 6;
            float zreg[64];
            #pragma unroll
            for (int e = 0; e < 64; e++) zreg[e] = zsh[e*65 + b];
            float best = 3.4e38f; int bk = 0;
            #pragma unroll 4
            for (int j = 0; j < 16; j++) {
                int kl = kg*16 + j;
                const float4* row = reinterpret_cast<const float4*>(cbs + kl*64);
                float d = 0.f;
                #pragma unroll
                for (int e4 = 0; e4 < 16; e4++) {
                    float4 c = row[e4];
                    float dx = zreg[4*e4]   - c.x; d = fmaf(dx, dx, d);
                    dx = zreg[4*e4+1] - c.y; d = fmaf(dx, dx, d);
                    dx = zreg[4*e4+2] - c.z; d = fmaf(dx, dx, d);
                    dx = zreg[4*e4+3] - c.w; d = fmaf(dx, dx, d);
                }
                if (d < best) { best = d; bk = kl; }
            }
            pdl[kg*64 + b] = best; pil[kg*64 + b] = bk;
            __syncthreads();
            if (tid < 64) {
                float bd = pdl[tid]; int bi = pil[tid];
                #pragma unroll
                for (int g = 1; g < 4; g++) {
                    float d2 = pdl[g*64 + tid];
                    if (d2 < bd) { bd = d2; bi = pil[g*64 + tid]; }
                }
                __stcg(&g_pd[blockIdx.x*64 + tid], bd);
                __stcg(&g_pi[blockIdx.x*64 + tid], kc*64 + bi);
            }
        }
        grid_barrier(gen);

        // ================= phase B: bid = b (finalize + stats + zq) =======
        {
            int b = blockIdx.x;
            float* cntc = (t & 1) ? g_cntB : g_cntA;
            float* sumc = (t & 1) ? g_sumB : g_sumA;

            // parallel finalize: tid<64 = (s, kc2); reduce width 8 via shfl
            if (tid < 64) {
                int s = tid >> 3, kc2 = tid & 7;
                float bd = __ldcg(&g_pd[(s*8 + kc2)*64 + b]);
                int   bi = __ldcg(&g_pi[(s*8 + kc2)*64 + b]);
                #pragma unroll
                for (int off = 4; off > 0; off >>= 1) {
                    float d2 = __shfl_down_sync(0xFFFFFFFFu, bd, off, 8);
                    int   k2 = __shfl_down_sync(0xFFFFFFFFu, bi, off, 8);
                    if (d2 < bd || (d2 == bd && k2 < bi)) { bd = d2; bi = k2; }
                }
                if (kc2 == 0) {
                    kmin[s] = bi; dmin[s] = bd;
                    atomicAdd(&cntc[bi], 1.0f);
                }
            }
            __syncthreads();
            if (tid == 0) {
                double e = 0.0;
                #pragma unroll
                for (int s = 0; s < 8; s++) e += (double)dmin[s];
                atomicAdd(&g_el, e * (1.0 / 32768.0));
            }
            #pragma unroll
            for (int rep = 0; rep < 2; rep++) {
                int j = tid + rep*256;
                int s = j >> 6, e = j & 63;
                int k = kmin[s];
                float zqv = __ldcg(&g_cb[((size_t)s*NK + k)*NE + e]);
                __stcg(&g_zq_all[((size_t)t*64 + b)*512 + j], zqv);
                atomicAdd(&sumc[k*64 + e], __ldcg(&zt[b*512 + j]));
            }
        }
        grid_barrier(gen);
    }
}

// ---------------- batched FiLM MLP over all (t,b): 8 rows/block ----------
__global__ __launch_bounds__(256) void k_mlpall(
        const float* __restrict__ m1w, const float* __restrict__ m1b,
        const float* __restrict__ m2w, const float* __restrict__ m2b) {
    int row0 = blockIdx.x * 8;          // 4032 rows total
    int tid = threadIdx.x;
    __shared__ float zq[8][512];
    __shared__ float h1s[8][128];
    {
        float4* dst = reinterpret_cast<float4*>(&zq[0][0]);
        const float4* src = reinterpret_cast<const float4*>(g_zq_all + (size_t)row0*512);
        #pragma unroll
        for (int rep = 0; rep < 4; rep++) dst[tid + rep*256] = src[tid + rep*256];
    }
    __syncthreads();
    {
        int col = tid & 127, half = tid >> 7;
        int r0 = half*4;
        float acc[4];
        float bv = m1b[col];
        #pragma unroll
        for (int r = 0; r < 4; r++) acc[r] = bv;
        for (int i = 0; i < 512; i++) {
            float wv = m1w[i*128 + col];
            #pragma unroll
            for (int r = 0; r < 4; r++) acc[r] = fmaf(zq[r0 + r][i], wv, acc[r]);
        }
        #pragma unroll
        for (int r = 0; r < 4; r++) h1s[r0 + r][col] = fmaxf(acc[r], 0.f);
    }
    __syncthreads();
    {
        float acc2[8];
        float bv = m2b[tid];
        #pragma unroll
        for (int r = 0; r < 8; r++) acc2[r] = bv;
        for (int i = 0; i < 128; i++) {
            float wv = m2w[i*256 + tid];
            #pragma unroll
            for (int r = 0; r < 8; r++) acc2[r] = fmaf(h1s[r][i], wv, acc2[r]);
        }
        #pragma unroll
        for (int r = 0; r < 8; r++) {
            int rr = row0 + r;          // = t*64 + b
            if (tid < 128) g_gab_g[(size_t)rr*128 + tid] = 1.f + acc2[r];
            else           g_gab_b[(size_t)rr*128 + (tid - 128)] = acc2[r];
        }
    }
}

// ---------------- batched decoder, 32 rows/block (halved weight traffic) --
__global__ __launch_bounds__(128) void k_dec(const int* __restrict__ acts,
        const float* __restrict__ w1, const float* __restrict__ b1,
        const float* __restrict__ w2, const float* __restrict__ b2,
        const float* __restrict__ w3, const float* __restrict__ b3) {
    int row0 = blockIdx.x * 32;
    int tp = row0 >> 6;
    int b0 = row0 & 63;
    float sq = sqrtf((float)(127*127 - 8*tp));
    int t = (int)((127.0f - sq) * 0.5f);
    while ((t+1)*(127-(t+1))/2 <= tp && t < 62) t++;
    while (t*(127-t)/2 > tp) t--;
    int p = t + (tp - t*(127-t)/2);
    int c = threadIdx.x;
    __shared__ float f[32][128];    // reused as h2 after layer 1
    __shared__ float h1[32][128];
    __shared__ float lg[32][6];
    __shared__ float ce[32];
    #pragma unroll
    for (int j = 0; j < 32; j++) {
        int b = b0 + j;
        float of = g_obs_feat[(b*64 + p)*NC + c];
        float fl = fmaf(of, g_gab_g[((size_t)t*64 + b)*128 + c],
                            g_gab_b[((size_t)t*64 + b)*128 + c]);
        f[j][c] = fmaxf(fl, 0.f);
    }
    __syncthreads();
    float acc[32];
    float bv = b1[c];
    #pragma unroll
    for (int j = 0; j < 32; j++) acc[j] = bv;
    for (int i = 0; i < 128; i += 4) {
        float wa = w1[i*128 + c], wb = w1[(i+1)*128 + c];
        float wc = w1[(i+2)*128 + c], wd = w1[(i+3)*128 + c];
        #pragma unroll
        for (int j = 0; j < 32; j++) {
            float4 fv = *reinterpret_cast<const float4*>(&f[j][i]);
            acc[j] = fmaf(fv.x, wa, fmaf(fv.y, wb, fmaf(fv.z, wc, fmaf(fv.w, wd, acc[j]))));
        }
    }
    __syncthreads();    // f fully consumed
    #pragma unroll
    for (int j = 0; j < 32; j++) h1[j][c] = fmaxf(acc[j], 0.f);
    __syncthreads();
    bv = b2[c];
    #pragma unroll
    for (int j = 0; j < 32; j++) acc[j] = bv;
    for (int i = 0; i < 128; i += 4) {
        float wa = w2[i*128 + c], wb = w2[(i+1)*128 + c];
        float wc = w2[(i+2)*128 + c], wd = w2[(i+3)*128 + c];
        #pragma unroll
        for (int j = 0; j < 32; j++) {
            float4 fv = *reinterpret_cast<const float4*>(&h1[j][i]);
            acc[j] = fmaf(fv.x, wa, fmaf(fv.y, wb, fmaf(fv.z, wc, fmaf(fv.w, wd, acc[j]))));
        }
    }
    #pragma unroll
    for (int j = 0; j < 32; j++) f[j][c] = fmaxf(acc[j], 0.f);   // h2 -> f storage
    __syncthreads();
    #pragma unroll
    for (int half = 0; half < 2; half++) {
        if (c < 96) {
            int j = half*16 + c / 6, o = c % 6;
            float l = b3[o];
            for (int i = 0; i < 128; i++) l = fmaf(f[j][i], w3[i*6 + o], l);
            lg[j][o] = l;
        }
    }
    __syncthreads();
    if (c < 32) {
        int b = b0 + c;
        float m = lg[c][0];
        #pragma unroll
        for (int i = 1; i < 6; i++) m = fmaxf(m, lg[c][i]);
        float se = 0.f;
        #pragma unroll
        for (int i = 0; i < 6; i++) se += expf(lg[c][i] - m);
        float lse = m + logf(se);
        int a = acts[b*63 + p];
        ce[c] = lse - lg[c][a];
    }
    __syncthreads();
    if (c == 0) {
        double ssum = 0.0;
        #pragma unroll
        for (int j = 0; j < 32; j++) ssum += (double)ce[j];
        atomicAdd(&g_decl, ssum);
    }
}

// ---------------- finalize ----------------
__global__ void k_final(float* __restrict__ out) {
    if (threadIdx.x == 0) {
        out[0] = (float)(g_decl / 64.0);
        out[1] = (float)(g_el / 64.0);
    }
}

// ---------------- launch ----------------
extern "C" void kernel_launch(void* const* d_in, const int* in_sizes, int n_in,
                              void* d_out, int out_size) {
    const int*   obs  = (const int*)d_in[0];
    const int*   acts = (const int*)d_in[1];
    const float* emb  = (const float*)d_in[2];
    const float* c1w  = (const float*)d_in[3];
    const float* c1b  = (const float*)d_in[4];
    const float* bn1g = (const float*)d_in[5];
    const float* bn1b = (const float*)d_in[6];
    const float* c2w  = (const float*)d_in[7];
    const float* c2b  = (const float*)d_in[8];
    const float* bn2g = (const float*)d_in[9];
    const float* bn2b = (const float*)d_in[10];
    const float* wih  = (const float*)d_in[11];
    const float* whh  = (const float*)d_in[12];
    const float* bih  = (const float*)d_in[13];
    const float* bhh  = (const float*)d_in[14];
    const float* prew = (const float*)d_in[15];
    const float* preb = (const float*)d_in[16];
    const float* cbk  = (const float*)d_in[17];
    const float* m1w  = (const float*)d_in[18];
    const float* m1b  = (const float*)d_in[19];
    const float* m2w  = (const float*)d_in[20];
    const float* m2b  = (const float*)d_in[21];
    const float* d1w  = (const float*)d_in[22];
    const float* d1b  = (const float*)d_in[23];
    const float* d2w  = (const float*)d_in[24];
    const float* d2b  = (const float*)d_in[25];
    const float* d3w  = (const float*)d_in[26];
    const float* d3b  = (const float*)d_in[27];
    float* out = (float*)d_out;

    cudaFuncSetAttribute(k_conv2, cudaFuncAttributeMaxDynamicSharedMemorySize, CONV_SMEM);

    k_wdup<<<576, 256>>>(c2w);                                   // 1: dup w2 + zero bn stats
    k_ew<<<441, 128>>>(emb, c1w);                                // 2: EW table
    k_conv1g<<<NIMG, 256>>>(obs, c1b);                           // 3: conv1 gather + bn1 stats
    k_conv2<<<NIMG, 128, CONV_SMEM>>>(c2b, bn2g, bn2b);          // 4: conv2 (ncu slot)
    k_init_a<<<1024, 256>>>(cbk);
    k_init_b<<<16, 256>>>();
    k_init_cde<<<128, 256>>>();
    k_bn2max<<<(NIMG*NC + 255)/256, 256>>>(bn2g, bn2b);
    k_gi<<<NIMG/8, 192>>>(wih, bih);
    k_zroll<<<NB, 256>>>(whh, bhh, prew, preb);
    k_scan<<<64, 256>>>();
    k_mlpall<<<NT*NB/8, 256>>>(m1w, m1b, m2w, m2b);
    k_dec<<<129024/32, 128>>>(acts, d1w, d1b, d2w, d2b, d3w, d3b);
    k_final<<<1, 32>>>(out);
}